// round 1
// baseline (speedup 1.0000x reference)
#include <cuda_runtime.h>
#include <cuda_bf16.h>
#include <math.h>

// Problem dims
// H=256, B=64, L=128, LABEL=128
// s = t*64 + b, S = 8192 total sequential cells.

#define NSTEPS 8192
#define NCTA   32

// Scratch (device globals: allocation-free rule)
__device__ float    g_G[8192u * 1024u];   // 32 MB: precomputed input gates + bias
__device__ float    g_H[8192u * 256u];    // 8 MB: h history (also final LSTM output)
__device__ unsigned g_done[NSTEPS];       // per-step arrival counters

// ---------------------------------------------------------------------------
// Kernel A: G[s][j] = sum_k feats[s][k] * W_ih[j][k]  (k<1024)  + b_ih[j] + b_hh[j]
// feats[s][k] = x[b][t][k] (k<512) else hi[b][t][k-512], with t=s>>6, b=s&63
// Tiled fp32 GEMM: M=8192, N=1024, K=1024. 64x64 tiles, BK=16, 256 threads.
// ---------------------------------------------------------------------------
__global__ void __launch_bounds__(256) gemm_gx_kernel(
    const float* __restrict__ x, const float* __restrict__ hi,
    const float* __restrict__ W_ih,
    const float* __restrict__ b_ih, const float* __restrict__ b_hh)
{
    __shared__ float As[16][68];
    __shared__ float Bs[16][68];

    const int tid = threadIdx.x;
    const int bn  = blockIdx.x;          // 0..15  (N tiles)
    const int bm  = blockIdx.y;          // 0..127 (M tiles)
    const int tx  = tid & 15;
    const int ty  = tid >> 4;

    const int lm  = tid >> 2;            // 0..63 load row
    const int lk4 = (tid & 3) * 4;       // 0,4,8,12

    // Precompute A-row source pointer base (row fixed across k tiles)
    const int s  = bm * 64 + lm;
    const int t  = s >> 6, b = s & 63;
    const float* xrow  = &x [((size_t)(b * 128 + t)) << 9];
    const float* hirow = &hi[((size_t)(b * 128 + t)) << 9];
    const float* wrow  = &W_ih[(size_t)(bn * 64 + (tid >> 2)) * 1280];

    float acc[4][4] = {};

    for (int kt = 0; kt < 64; kt++) {
        const int kbase = kt * 16 + lk4;
        // load A tile (transposed into As[k][m])
        float4 av;
        if (kbase < 512) av = *(const float4*)&xrow[kbase];
        else             av = *(const float4*)&hirow[kbase - 512];
        As[lk4 + 0][lm] = av.x;
        As[lk4 + 1][lm] = av.y;
        As[lk4 + 2][lm] = av.z;
        As[lk4 + 3][lm] = av.w;
        // load B tile: W_ih[j][k], j = bn*64 + (tid>>2)
        float4 bv = *(const float4*)&wrow[kbase];
        Bs[lk4 + 0][tid >> 2] = bv.x;
        Bs[lk4 + 1][tid >> 2] = bv.y;
        Bs[lk4 + 2][tid >> 2] = bv.z;
        Bs[lk4 + 3][tid >> 2] = bv.w;
        __syncthreads();

#pragma unroll
        for (int kk = 0; kk < 16; kk++) {
            float ar[4], br[4];
#pragma unroll
            for (int i = 0; i < 4; i++) ar[i] = As[kk][ty * 4 + i];
#pragma unroll
            for (int j = 0; j < 4; j++) br[j] = Bs[kk][tx * 4 + j];
#pragma unroll
            for (int i = 0; i < 4; i++)
#pragma unroll
                for (int j = 0; j < 4; j++)
                    acc[i][j] = fmaf(ar[i], br[j], acc[i][j]);
        }
        __syncthreads();
    }

    // epilogue: add bias, store
    const int col0 = bn * 64 + tx * 4;
    float bias[4];
#pragma unroll
    for (int j = 0; j < 4; j++) bias[j] = b_ih[col0 + j] + b_hh[col0 + j];
#pragma unroll
    for (int i = 0; i < 4; i++) {
        const size_t row = (size_t)(bm * 64 + ty * 4 + i);
        float4 v;
        v.x = acc[i][0] + bias[0];
        v.y = acc[i][1] + bias[1];
        v.z = acc[i][2] + bias[2];
        v.w = acc[i][3] + bias[3];
        *(float4*)&g_G[row * 1024 + col0] = v;
    }
}

// ---------------------------------------------------------------------------
// Kernel B: the sequential chain. 32 persistent CTAs x 256 threads.
// CTA k owns h-indices j = k*8 .. k*8+7 (8 of 256), i.e. 32 gate rows
// (4 gates x 8). Weights [W_hh | W_r] for those rows live in REGISTERS:
// thread (rg,cg): rows r0=2*rg, r1=2*rg+1 (local), cols cg*32..cg*32+31.
// Per-step sync: global arrival counter in L2 (release/acquire).
// ---------------------------------------------------------------------------
__device__ __forceinline__ unsigned ld_acq(const unsigned* p) {
    unsigned v;
    asm volatile("ld.acquire.gpu.global.b32 %0, [%1];" : "=r"(v) : "l"(p) : "memory");
    return v;
}

__global__ void __launch_bounds__(256, 1) chain_kernel(
    const float* __restrict__ W_ih, const float* __restrict__ W_hh)
{
    __shared__ float vsh[16 * 33];   // 512-vector [h | out_prev], padded layout
    __shared__ float garr[32];       // the CTA's 32 gate pre-activations
    __shared__ float csh[8];         // cell state slice

    const int tid = threadIdx.x;
    const int k   = blockIdx.x;      // 0..31
    const int cg  = tid & 15;        // col group (32 cols each)
    const int rg  = tid >> 4;        // row group (2 rows each), 0..15

    const int r0 = rg * 2, r1 = r0 + 1;
    const int grow0 = (r0 >> 3) * 256 + k * 8 + (r0 & 7);
    const int grow1 = (r1 >> 3) * 256 + k * 8 + (r1 & 7);

    // Load weights into registers. col c' < 256 -> W_hh, else W_ih[:,1024+c'-256]
    float w0[32], w1[32];
#pragma unroll
    for (int c = 0; c < 32; c++) {
        const int ccol = cg * 32 + c;
        if (ccol < 256) {
            w0[c] = W_hh[(size_t)grow0 * 256 + ccol];
            w1[c] = W_hh[(size_t)grow1 * 256 + ccol];
        } else {
            w0[c] = W_ih[(size_t)grow0 * 1280 + 768 + ccol];
            w1[c] = W_ih[(size_t)grow1 * 1280 + 768 + ccol];
        }
    }

    if (tid < 8) csh[tid] = 0.f;

    for (int s = 0; s < NSTEPS; s++) {
        // wait until h[s-1] fully published
        if (s > 0) {
            if (tid == 0) {
                while (ld_acq(&g_done[s - 1]) < NCTA) { }
            }
            __syncthreads();
        }
        // gather v = [h(s-1) | out_prev = h(s-64)] into padded smem
        {
            float hv = (s > 0)   ? __ldcg(&g_H[(size_t)(s - 1)  * 256 + tid]) : 0.f;
            float ov = (s >= 64) ? __ldcg(&g_H[(size_t)(s - 64) * 256 + tid]) : 0.f;
            vsh[(tid >> 5) * 33 + (tid & 31)] = hv;
            const int e = 256 + tid;
            vsh[(e >> 5) * 33 + (e & 31)] = ov;
        }
        __syncthreads();

        // matvec partials
        float a0 = 0.f, a1 = 0.f;
        const float* vb = &vsh[cg * 33];
#pragma unroll
        for (int c = 0; c < 32; c++) {
            const float vv = vb[c];
            a0 = fmaf(w0[c], vv, a0);
            a1 = fmaf(w1[c], vv, a1);
        }
        // reduce across the 16 col-groups (lower/upper 16 lanes of each warp)
#pragma unroll
        for (int off = 1; off < 16; off <<= 1) {
            a0 += __shfl_xor_sync(0xffffffffu, a0, off);
            a1 += __shfl_xor_sync(0xffffffffu, a1, off);
        }
        if (cg == 0) {
            const size_t gb = (size_t)s * 1024;
            garr[r0] = a0 + __ldcg(&g_G[gb + grow0]);
            garr[r1] = a1 + __ldcg(&g_G[gb + grow1]);
        }
        __syncthreads();

        // gates + state update + publish h slice
        if (tid < 8) {
            const float gi = garr[tid];
            const float gf = garr[8 + tid];
            const float gg = garr[16 + tid];
            const float go = garr[24 + tid];
            const float iv = 1.f / (1.f + __expf(-gi));
            const float fv = 1.f / (1.f + __expf(-gf));
            const float gv = tanhf(gg);
            const float ov = 1.f / (1.f + __expf(-go));
            const float cv = fv * csh[tid] + iv * gv;
            csh[tid] = cv;
            const float hv = ov * tanhf(cv);
            __stcg(&g_H[(size_t)s * 256 + k * 8 + tid], hv);
            __threadfence();   // make h visible at gpu scope before arrival
        }
        __syncthreads();
        if (tid == 0) atomicAdd(&g_done[s], 1u);
    }
}

// ---------------------------------------------------------------------------
// Kernel C: out[b][t][l] = sum_j H[s][j] * W_fc[l][j] + b_fc[l], s = t*64+b
// ---------------------------------------------------------------------------
__global__ void __launch_bounds__(128) fc_kernel(
    const float* __restrict__ W_fc, const float* __restrict__ b_fc,
    float* __restrict__ out)
{
    __shared__ float hrow[256];
    const int s = blockIdx.x;
    const int l = threadIdx.x;
    hrow[l]       = g_H[(size_t)s * 256 + l];
    hrow[128 + l] = g_H[(size_t)s * 256 + 128 + l];
    __syncthreads();

    float acc = b_fc[l];
    const float* wr = &W_fc[(size_t)l * 256];
#pragma unroll 8
    for (int j = 0; j < 256; j++) acc = fmaf(wr[j], hrow[j], acc);

    const int t = s >> 6, b = s & 63;
    out[((size_t)b << 14) + (size_t)t * 128 + l] = acc;  // b*L*LABEL + t*LABEL + l
}

// ---------------------------------------------------------------------------
extern "C" void kernel_launch(void* const* d_in, const int* in_sizes, int n_in,
                              void* d_out, int out_size)
{
    const float* x    = (const float*)d_in[0];
    const float* hi   = (const float*)d_in[1];
    const float* W_ih = (const float*)d_in[2];
    const float* W_hh = (const float*)d_in[3];
    const float* b_ih = (const float*)d_in[4];
    const float* b_hh = (const float*)d_in[5];
    const float* W_fc = (const float*)d_in[6];
    const float* b_fc = (const float*)d_in[7];
    float* out = (float*)d_out;

    void* donep = nullptr;
    cudaGetSymbolAddress(&donep, g_done);
    cudaMemsetAsync(donep, 0, NSTEPS * sizeof(unsigned));

    gemm_gx_kernel<<<dim3(16, 128), 256>>>(x, hi, W_ih, b_ih, b_hh);
    chain_kernel<<<NCTA, 256>>>(W_ih, W_hh);
    fc_kernel<<<NSTEPS, 128>>>(W_fc, b_fc, out);
}

// round 4
// speedup vs baseline: 1.1693x; 1.1693x over previous
#include <cuda_runtime.h>
#include <cuda_bf16.h>
#include <math.h>

// Problem dims: H=256, B=64, L=128, LABEL=128
// s = t*64 + b, S = 8192 sequential cells.

#define NSTEPS 8192
#define NCTA   32

// Scratch (device globals: allocation-free rule)
__device__ float    g_G[8192u * 1024u];   // 32 MB: precomputed input gates + bias
__device__ float    g_H[8192u * 256u];    // 8 MB: h history
__device__ unsigned g_flag[8192u * 256u]; // 8 MB: per-(step, h-index) publish flags

// ---------------------------------------------------------------------------
// release/acquire helpers (gpu scope)
// ---------------------------------------------------------------------------
__device__ __forceinline__ unsigned ld_acq(const unsigned* p) {
    unsigned v;
    asm volatile("ld.acquire.gpu.global.b32 %0, [%1];" : "=r"(v) : "l"(p) : "memory");
    return v;
}
__device__ __forceinline__ void st_rel(unsigned* p, unsigned v) {
    asm volatile("st.release.gpu.global.b32 [%0], %1;" :: "l"(p), "r"(v) : "memory");
}

// ---------------------------------------------------------------------------
// Kernel A: G[s][j] = feats[s] . W_ih[j][0:1024] + b_ih[j] + b_hh[j]
// Tiled fp32 GEMM: M=8192, N=1024, K=1024.  (proven: 489us)
// ---------------------------------------------------------------------------
__global__ void __launch_bounds__(256) gemm_gx_kernel(
    const float* __restrict__ x, const float* __restrict__ hi,
    const float* __restrict__ W_ih,
    const float* __restrict__ b_ih, const float* __restrict__ b_hh)
{
    __shared__ float As[16][68];
    __shared__ float Bs[16][68];

    const int tid = threadIdx.x;
    const int bn  = blockIdx.x;          // 0..15  (N tiles)
    const int bm  = blockIdx.y;          // 0..127 (M tiles)
    const int tx  = tid & 15;
    const int ty  = tid >> 4;

    const int lm  = tid >> 2;            // 0..63 load row
    const int lk4 = (tid & 3) * 4;       // 0,4,8,12

    const int s  = bm * 64 + lm;
    const int t  = s >> 6, b = s & 63;
    const float* xrow  = &x [((size_t)(b * 128 + t)) << 9];
    const float* hirow = &hi[((size_t)(b * 128 + t)) << 9];
    const float* wrow  = &W_ih[(size_t)(bn * 64 + (tid >> 2)) * 1280];

    float acc[4][4] = {};

    for (int kt = 0; kt < 64; kt++) {
        const int kbase = kt * 16 + lk4;
        float4 av;
        if (kbase < 512) av = *(const float4*)&xrow[kbase];
        else             av = *(const float4*)&hirow[kbase - 512];
        As[lk4 + 0][lm] = av.x;
        As[lk4 + 1][lm] = av.y;
        As[lk4 + 2][lm] = av.z;
        As[lk4 + 3][lm] = av.w;
        float4 bv = *(const float4*)&wrow[kbase];
        Bs[lk4 + 0][tid >> 2] = bv.x;
        Bs[lk4 + 1][tid >> 2] = bv.y;
        Bs[lk4 + 2][tid >> 2] = bv.z;
        Bs[lk4 + 3][tid >> 2] = bv.w;
        __syncthreads();

#pragma unroll
        for (int kk = 0; kk < 16; kk++) {
            float ar[4], br[4];
#pragma unroll
            for (int i = 0; i < 4; i++) ar[i] = As[kk][ty * 4 + i];
#pragma unroll
            for (int j = 0; j < 4; j++) br[j] = Bs[kk][tx * 4 + j];
#pragma unroll
            for (int i = 0; i < 4; i++)
#pragma unroll
                for (int j = 0; j < 4; j++)
                    acc[i][j] = fmaf(ar[i], br[j], acc[i][j]);
        }
        __syncthreads();
    }

    const int col0 = bn * 64 + tx * 4;
    float bias[4];
#pragma unroll
    for (int j = 0; j < 4; j++) bias[j] = b_ih[col0 + j] + b_hh[col0 + j];
#pragma unroll
    for (int i = 0; i < 4; i++) {
        const size_t row = (size_t)(bm * 64 + ty * 4 + i);
        float4 v;
        v.x = acc[i][0] + bias[0];
        v.y = acc[i][1] + bias[1];
        v.z = acc[i][2] + bias[2];
        v.w = acc[i][3] + bias[3];
        *(float4*)&g_G[row * 1024 + col0] = v;
    }
}

// ---------------------------------------------------------------------------
// Kernel B: sequential chain. 32 persistent CTAs x 256 threads.
// CTA k owns h indices k*8..k*8+7 (32 gate rows). Weights register-resident
// (R1-proven layout). Sync: per-(step,h-index) flags. Producer thread tid<8
// stores its h word (st.cg) then release-stores its flag: program order makes
// the release publish that thread's h[s] AND (transitively, via its earlier
// releases) h[s-64]. Consumer thread tid acquire-polls flag[(s-1)*256+tid]
// only, then plain-loads h[s-1][tid] and h[s-64][tid].
// ---------------------------------------------------------------------------
__global__ void __launch_bounds__(256, 1) chain_kernel(
    const float* __restrict__ W_ih, const float* __restrict__ W_hh)
{
    __shared__ float vsh[16 * 33];   // 512-vector [h | out_prev], padded (R1)
    __shared__ float garr[32];
    __shared__ float csh[8];

    const int tid = threadIdx.x;
    const int k   = blockIdx.x;      // 0..31
    const int cg  = tid & 15;        // col group (32 cols each)
    const int rg  = tid >> 4;        // row group (2 rows each)

    const int r0 = rg * 2, r1 = r0 + 1;
    const int grow0 = (r0 >> 3) * 256 + k * 8 + (r0 & 7);
    const int grow1 = (r1 >> 3) * 256 + k * 8 + (r1 & 7);

    // Register-resident weights (verbatim R1)
    float w0[32], w1[32];
#pragma unroll
    for (int c = 0; c < 32; c++) {
        const int ccol = cg * 32 + c;
        if (ccol < 256) {
            w0[c] = W_hh[(size_t)grow0 * 256 + ccol];
            w1[c] = W_hh[(size_t)grow1 * 256 + ccol];
        } else {
            w0[c] = W_ih[(size_t)grow0 * 1280 + 768 + ccol];
            w1[c] = W_ih[(size_t)grow1 * 1280 + 768 + ccol];
        }
    }

    if (tid < 8) csh[tid] = 0.f;

    for (int s = 0; s < NSTEPS; s++) {
        __syncthreads();   // prev step's vsh/garr reads complete

        // prefetch this step's G rows (independent of the wait)
        float gp0 = 0.f, gp1 = 0.f;
        if (cg == 0) {
            const size_t gb = (size_t)s * 1024;
            gp0 = __ldcg(&g_G[gb + grow0]);
            gp1 = __ldcg(&g_G[gb + grow1]);
        }

        // wait + gather: thread tid handles h-index tid
        float hv = 0.f, ov = 0.f;
        if (s > 0) {
            while (ld_acq(&g_flag[(size_t)(s - 1) * 256 + tid]) == 0u) { }
            hv = __ldcg(&g_H[(size_t)(s - 1) * 256 + tid]);
            if (s >= 64)
                ov = __ldcg(&g_H[(size_t)(s - 64) * 256 + tid]);
        }
        vsh[(tid >> 5) * 33 + (tid & 31)] = hv;
        {
            const int e = 256 + tid;
            vsh[(e >> 5) * 33 + (e & 31)] = ov;
        }
        __syncthreads();

        // matvec partials (verbatim R1)
        float a0 = 0.f, a1 = 0.f;
        const float* vb = &vsh[cg * 33];
#pragma unroll
        for (int c = 0; c < 32; c++) {
            const float vv = vb[c];
            a0 = fmaf(w0[c], vv, a0);
            a1 = fmaf(w1[c], vv, a1);
        }
#pragma unroll
        for (int off = 1; off < 16; off <<= 1) {
            a0 += __shfl_xor_sync(0xffffffffu, a0, off);
            a1 += __shfl_xor_sync(0xffffffffu, a1, off);
        }
        if (cg == 0) {
            garr[r0] = a0 + gp0;
            garr[r1] = a1 + gp1;
        }
        __syncthreads();

        // gates + state update + publish (store h, then release own flag)
        if (tid < 8) {
            const float gi = garr[tid];
            const float gf = garr[8 + tid];
            const float gg = garr[16 + tid];
            const float go = garr[24 + tid];
            const float iv = 1.f / (1.f + __expf(-gi));
            const float fv = 1.f / (1.f + __expf(-gf));
            const float gv = tanhf(gg);
            const float ovv = 1.f / (1.f + __expf(-go));
            const float cv = fv * csh[tid] + iv * gv;
            csh[tid] = cv;
            const float hvout = ovv * tanhf(cv);
            const size_t hidx = (size_t)s * 256 + k * 8 + tid;
            __stcg(&g_H[hidx], hvout);
            st_rel(&g_flag[hidx], 1u);
        }
    }
}

// ---------------------------------------------------------------------------
// Kernel C: out[b][t][l] = H[s] . W_fc[l] + b_fc[l], s = t*64+b
// ---------------------------------------------------------------------------
__global__ void __launch_bounds__(128) fc_kernel(
    const float* __restrict__ W_fc, const float* __restrict__ b_fc,
    float* __restrict__ out)
{
    __shared__ float hrow[256];
    const int s = blockIdx.x;
    const int l = threadIdx.x;
    hrow[l]       = g_H[(size_t)s * 256 + l];
    hrow[128 + l] = g_H[(size_t)s * 256 + 128 + l];
    __syncthreads();

    float acc = b_fc[l];
    const float* wr = &W_fc[(size_t)l * 256];
#pragma unroll 8
    for (int j = 0; j < 256; j++) acc = fmaf(wr[j], hrow[j], acc);

    const int t = s >> 6, b = s & 63;
    out[((size_t)b << 14) + (size_t)t * 128 + l] = acc;
}

// ---------------------------------------------------------------------------
extern "C" void kernel_launch(void* const* d_in, const int* in_sizes, int n_in,
                              void* d_out, int out_size)
{
    const float* x    = (const float*)d_in[0];
    const float* hi   = (const float*)d_in[1];
    const float* W_ih = (const float*)d_in[2];
    const float* W_hh = (const float*)d_in[3];
    const float* b_ih = (const float*)d_in[4];
    const float* b_hh = (const float*)d_in[5];
    const float* W_fc = (const float*)d_in[6];
    const float* b_fc = (const float*)d_in[7];
    float* out = (float*)d_out;

    // zero the publish flags every call/replay
    void* fp = nullptr;
    cudaGetSymbolAddress(&fp, g_flag);
    cudaMemsetAsync(fp, 0, 8192u * 256u * sizeof(unsigned));

    gemm_gx_kernel<<<dim3(16, 128), 256>>>(x, hi, W_ih, b_ih, b_hh);
    chain_kernel<<<NCTA, 256>>>(W_ih, W_hh);
    fc_kernel<<<NSTEPS, 128>>>(W_fc, b_fc, out);
}